// round 9
// baseline (speedup 1.0000x reference)
#include <cuda_runtime.h>
#include <math.h>

#define NN 20000
#define FF 8
#define PP 12
#define OO 32
#define EE 320000
#define FP 96           // F*P floats per node row
#define SLOTS 96        // max in-degree slots (Poisson(16); guarded)
#define NSM 148
#define NBPS 3
#define NBLK (NSM * NBPS)            // 444 blocks, all co-resident
#define NTHR 256
#define WPB (NTHR / 32)              // 8 warps per block
#define FULL 0xffffffffu

// ---- scratch (static device globals; no allocation allowed) ----
__device__ int      g_cnt[NN];            // in-degree (atomic counters)
__device__ int      g_col[NN * SLOTS];    // slotted adjacency: srcs per dst
__device__ float    g_dinv[NN];           // (in_deg + 1)^-1/2
__device__ float    g_cwz[FF * OO];       // fused Wz @ Lz^T
__device__ float    g_cwh[FF * OO];       // fused Wh @ Lh^T
__device__ float    g_cbz[OO];
__device__ float    g_cbh[OO];
__device__ float    g_probs[PP];
__device__ unsigned g_node_ctr;           // P3 dynamic work counter (reset in P2)
__device__ unsigned g_bar[3];             // monotonic barrier counters (never reset)

// Monotonic grid barrier: all NBLK blocks co-resident (3/SM via launch bounds).
__device__ __forceinline__ void grid_barrier(int id) {
    __syncthreads();
    if (threadIdx.x == 0) {
        __threadfence();                                      // release
        unsigned arrived = atomicAdd(&g_bar[id], 1u) + 1u;
        unsigned target  = ((arrived + NBLK - 1u) / NBLK) * NBLK;
        while (*(volatile unsigned*)&g_bar[id] < target) { }
        __threadfence();                                      // acquire
    }
    __syncthreads();
}

// Packed fp32x2 helpers (Blackwell FFMA2 — only reachable via PTX)
__device__ __forceinline__ unsigned long long pack2(float lo, float hi) {
    unsigned long long r;
    asm("mov.b64 %0, {%1, %2};" : "=l"(r) : "f"(lo), "f"(hi));
    return r;
}
__device__ __forceinline__ void unpack2(unsigned long long v, float& lo, float& hi) {
    asm("mov.b64 {%0, %1}, %2;" : "=f"(lo), "=f"(hi) : "l"(v));
}
__device__ __forceinline__ unsigned long long ffma2(
        unsigned long long a, unsigned long long b, unsigned long long c) {
    unsigned long long d;
    asm("fma.rn.f32x2 %0, %1, %2, %3;" : "=l"(d) : "l"(a), "l"(b), "l"(c));
    return d;
}
// HW tanh (MUFU.TANH), rel err ~1e-5 — far inside the 1e-3 budget
__device__ __forceinline__ float htanh(float x) {
    float r;
    asm("tanh.approx.f32 %0, %1;" : "=f"(r) : "f"(x));
    return r;
}

__global__ void __launch_bounds__(NTHR, NBPS) fused_kernel(
        const float* __restrict__ x,
        const int*   __restrict__ ei,
        const float* __restrict__ Wz,  const float* __restrict__ bz,
        const float* __restrict__ Wh,  const float* __restrict__ bh,
        const float* __restrict__ lzw, const float* __restrict__ lzb,
        const float* __restrict__ lhw, const float* __restrict__ lhb,
        const float* __restrict__ att,
        const float* __restrict__ out_w, const float* __restrict__ out_b,
        float* __restrict__ out) {
    const int t    = threadIdx.x;
    const int lane = t & 31;
    const int warp = t >> 5;                 // 0..7
    const int gid  = blockIdx.x * NTHR + t;
    const int T    = NBLK * NTHR;

    __shared__ float buf[WPB][2][FP];        // GRU staging, per warp, 2 nodes
    __shared__ float sow[PP * OO];           // staged out_w
    __shared__ float sob[PP];                // staged out_b
    __shared__ float sp2[PP];                // 0.5 * softmax(att)

    // ---------------- P0: zero counters + fold weights (blocks 0..2) -------
    for (int j = gid; j < NN; j += T) g_cnt[j] = 0;

    if (blockIdx.x == 0) {                   // W'_z[f][o] = sum_k Wz[f][k]*lzw[o][k]
        int f = t >> 5, o = t & 31;
        float s = 0.f;
        #pragma unroll
        for (int k = 0; k < 32; ++k) s = fmaf(Wz[f * 32 + k], lzw[o * 64 + k], s);
        g_cwz[t] = s;
    } else if (blockIdx.x == 1) {            // W'_h
        int f = t >> 5, o = t & 31;
        float s = 0.f;
        #pragma unroll
        for (int k = 0; k < 32; ++k) s = fmaf(Wh[f * 32 + k], lhw[o * 64 + k], s);
        g_cwh[t] = s;
    } else if (blockIdx.x == 2) {
        if (t < 32) {                        // b'_z
            float s = lzb[t];
            #pragma unroll
            for (int k = 0; k < 32; ++k) s = fmaf(bz[k], lzw[t * 64 + k], s);
            g_cbz[t] = s;
        } else if (t < 64) {                 // b'_h
            int o = t - 32;
            float s = lhb[o];
            #pragma unroll
            for (int k = 0; k < 32; ++k) s = fmaf(bh[k], lhw[o * 64 + k], s);
            g_cbh[o] = s;
        } else if (t == 64) {                // softmax over 12 logits
            float m = att[0];
            for (int p = 1; p < PP; ++p) m = fmaxf(m, att[p]);
            float e[PP], sum = 0.f;
            for (int p = 0; p < PP; ++p) { e[p] = __expf(att[p] - m); sum += e[p]; }
            float inv = 1.f / sum;
            for (int p = 0; p < PP; ++p) g_probs[p] = e[p] * inv;
        }
    }
    grid_barrier(0);

    // ---------------- P1: single-pass slotted scatter -----------------------
    {
        const int4* s4p = (const int4*)ei;
        const int4* d4p = (const int4*)(ei + EE);
        for (int q = gid; q < EE / 4; q += T) {
            int4 s4 = s4p[q];
            int4 d4 = d4p[q];
            int p0 = atomicAdd(&g_cnt[d4.x], 1);
            int p1 = atomicAdd(&g_cnt[d4.y], 1);
            int p2 = atomicAdd(&g_cnt[d4.z], 1);
            int p3 = atomicAdd(&g_cnt[d4.w], 1);
            if (p0 < SLOTS) g_col[d4.x * SLOTS + p0] = s4.x;
            if (p1 < SLOTS) g_col[d4.y * SLOTS + p1] = s4.y;
            if (p2 < SLOTS) g_col[d4.z * SLOTS + p2] = s4.z;
            if (p3 < SLOTS) g_col[d4.w * SLOTS + p3] = s4.w;
        }
    }
    grid_barrier(1);

    // ---------------- P2: dinv + reset node counter ------------------------
    for (int j = gid; j < NN; j += T)
        g_dinv[j] = rsqrtf((float)(__ldcg(&g_cnt[j]) + 1));
    if (gid == 0) g_node_ctr = 0;
    grid_barrier(2);

    // ---------------- P3: gather(x2) + GRU + attention + readout -----------
    {
        if (t < PP) sp2[t] = 0.5f * g_probs[t];   // fold sigmoid's 0.5
        if (t < PP) sob[t] = out_b[t];
        for (int j = t; j < PP * OO; j += NTHR) sow[j] = out_w[j];
        __syncthreads();

        float wz[FF], wh[FF];
        #pragma unroll
        for (int f = 0; f < FF; ++f) {
            wz[f] = g_cwz[f * OO + lane];
            wh[f] = g_cwh[f * OO + lane];
        }
        const float bz_ = g_cbz[lane];
        const float bh_ = g_cbh[lane];

        for (;;) {
            int base;
            if (lane == 0) base = (int)atomicAdd(&g_node_ctr, 2u);
            base = __shfl_sync(FULL, base, 0);
            if (base >= NN) break;
            const int nA = base, nB = base + 1;   // NN even -> both valid

            int degA = g_cnt[nA]; if (degA > SLOTS) degA = SLOTS;
            int degB = g_cnt[nB]; if (degB > SLOTS) degB = SLOTS;
            const int* colsA = g_col + nA * SLOTS;
            const int* colsB = g_col + nB * SLOTS;
            float diA = g_dinv[nA];
            float diB = g_dinv[nB];

            float4 accA = make_float4(0.f, 0.f, 0.f, 0.f);
            float4 accB = make_float4(0.f, 0.f, 0.f, 0.f);

            int maxdeg = degA > degB ? degA : degB;
            for (int b = 0; b < maxdeg; b += 32) {
                int nbA = degA - b; nbA = nbA < 0 ? 0 : (nbA > 32 ? 32 : nbA);
                int nbB = degB - b; nbB = nbB < 0 ? 0 : (nbB > 32 ? 32 : nbB);
                // 4 independent LDG chains (A-cols, B-cols, A-dinv, B-dinv)
                int   ciA = (lane < nbA) ? __ldg(&colsA[b + lane]) : 0;
                int   ciB = (lane < nbB) ? __ldg(&colsB[b + lane]) : 0;
                float wA  = (lane < nbA) ? __ldg(&g_dinv[ciA])     : 0.f;
                float wB  = (lane < nbB) ? __ldg(&g_dinv[ciB])     : 0.f;

                int nbm = nbA > nbB ? nbA : nbB;
                nbm = (nbm + 3) & ~3;
                // padding lanes carry (idx=0, w=0): loads hit x row 0 in L1,
                // FMAs add zero -> branch-free inner loop, 8 LDGs in flight
                for (int k = 0; k < nbm; k += 4) {
                    int   a0 = __shfl_sync(FULL, ciA, k);
                    int   a1 = __shfl_sync(FULL, ciA, k + 1);
                    int   a2 = __shfl_sync(FULL, ciA, k + 2);
                    int   a3 = __shfl_sync(FULL, ciA, k + 3);
                    int   b0 = __shfl_sync(FULL, ciB, k);
                    int   b1 = __shfl_sync(FULL, ciB, k + 1);
                    int   b2 = __shfl_sync(FULL, ciB, k + 2);
                    int   b3 = __shfl_sync(FULL, ciB, k + 3);
                    float p0 = __shfl_sync(FULL, wA, k);
                    float p1 = __shfl_sync(FULL, wA, k + 1);
                    float p2 = __shfl_sync(FULL, wA, k + 2);
                    float p3 = __shfl_sync(FULL, wA, k + 3);
                    float q0 = __shfl_sync(FULL, wB, k);
                    float q1 = __shfl_sync(FULL, wB, k + 1);
                    float q2 = __shfl_sync(FULL, wB, k + 2);
                    float q3 = __shfl_sync(FULL, wB, k + 3);
                    if (lane < 24) {
                        float4 vA0 = __ldg((const float4*)(x + (size_t)a0 * FP) + lane);
                        float4 vA1 = __ldg((const float4*)(x + (size_t)a1 * FP) + lane);
                        float4 vA2 = __ldg((const float4*)(x + (size_t)a2 * FP) + lane);
                        float4 vA3 = __ldg((const float4*)(x + (size_t)a3 * FP) + lane);
                        float4 vB0 = __ldg((const float4*)(x + (size_t)b0 * FP) + lane);
                        float4 vB1 = __ldg((const float4*)(x + (size_t)b1 * FP) + lane);
                        float4 vB2 = __ldg((const float4*)(x + (size_t)b2 * FP) + lane);
                        float4 vB3 = __ldg((const float4*)(x + (size_t)b3 * FP) + lane);
                        accA.x = fmaf(p0, vA0.x, accA.x); accA.y = fmaf(p0, vA0.y, accA.y);
                        accA.z = fmaf(p0, vA0.z, accA.z); accA.w = fmaf(p0, vA0.w, accA.w);
                        accA.x = fmaf(p1, vA1.x, accA.x); accA.y = fmaf(p1, vA1.y, accA.y);
                        accA.z = fmaf(p1, vA1.z, accA.z); accA.w = fmaf(p1, vA1.w, accA.w);
                        accA.x = fmaf(p2, vA2.x, accA.x); accA.y = fmaf(p2, vA2.y, accA.y);
                        accA.z = fmaf(p2, vA2.z, accA.z); accA.w = fmaf(p2, vA2.w, accA.w);
                        accA.x = fmaf(p3, vA3.x, accA.x); accA.y = fmaf(p3, vA3.y, accA.y);
                        accA.z = fmaf(p3, vA3.z, accA.z); accA.w = fmaf(p3, vA3.w, accA.w);
                        accB.x = fmaf(q0, vB0.x, accB.x); accB.y = fmaf(q0, vB0.y, accB.y);
                        accB.z = fmaf(q0, vB0.z, accB.z); accB.w = fmaf(q0, vB0.w, accB.w);
                        accB.x = fmaf(q1, vB1.x, accB.x); accB.y = fmaf(q1, vB1.y, accB.y);
                        accB.z = fmaf(q1, vB1.z, accB.z); accB.w = fmaf(q1, vB1.w, accB.w);
                        accB.x = fmaf(q2, vB2.x, accB.x); accB.y = fmaf(q2, vB2.y, accB.y);
                        accB.z = fmaf(q2, vB2.z, accB.z); accB.w = fmaf(q2, vB2.w, accB.w);
                        accB.x = fmaf(q3, vB3.x, accB.x); accB.y = fmaf(q3, vB3.y, accB.y);
                        accB.z = fmaf(q3, vB3.z, accB.z); accB.w = fmaf(q3, vB3.w, accB.w);
                    }
                }
            }

            // agg = di * (acc + di * x_self); stage both nodes to smem
            if (lane < 24) {
                float4 xvA = __ldg((const float4*)(x + (size_t)nA * FP) + lane);
                float4 xvB = __ldg((const float4*)(x + (size_t)nB * FP) + lane);
                accA.x = diA * fmaf(diA, xvA.x, accA.x);
                accA.y = diA * fmaf(diA, xvA.y, accA.y);
                accA.z = diA * fmaf(diA, xvA.z, accA.z);
                accA.w = diA * fmaf(diA, xvA.w, accA.w);
                accB.x = diB * fmaf(diB, xvB.x, accB.x);
                accB.y = diB * fmaf(diB, xvB.y, accB.y);
                accB.z = diB * fmaf(diB, xvB.z, accB.z);
                accB.w = diB * fmaf(diB, xvB.w, accB.w);
                ((float4*)buf[warp][0])[lane] = accA;
                ((float4*)buf[warp][1])[lane] = accB;
            }
            __syncwarp();

            // ---- GRU + readout for both nodes ------------------------------
            #pragma unroll
            for (int i = 0; i < 2; ++i) {
                const float* bw = buf[warp][i];
                unsigned long long zp[PP / 2], hp[PP / 2];
                {
                    unsigned long long bz2 = pack2(bz_, bz_);
                    unsigned long long bh2 = pack2(bh_, bh_);
                    #pragma unroll
                    for (int q = 0; q < PP / 2; ++q) { zp[q] = bz2; hp[q] = bh2; }
                }
                #pragma unroll
                for (int f = 0; f < FF; ++f) {
                    unsigned long long wz2 = pack2(wz[f], wz[f]);
                    unsigned long long wh2 = pack2(wh[f], wh[f]);
                    #pragma unroll
                    for (int q = 0; q < PP / 2; ++q) {
                        unsigned long long v2 =
                            *(const unsigned long long*)&bw[f * PP + 2 * q];
                        zp[q] = ffma2(v2, wz2, zp[q]);
                        hp[q] = ffma2(v2, wh2, hp[q]);
                    }
                }
                // probs*(1-Z)*tanh(h), Z = 0.5 + 0.5*tanh(z/2)
                //   => (0.5*probs) * (1 - tanh(z/2)) * tanh(h)
                float hacc = 0.f;
                #pragma unroll
                for (int q = 0; q < PP / 2; ++q) {
                    float z0, z1, h0, h1;
                    unpack2(zp[q], z0, z1);
                    unpack2(hp[q], h0, h1);
                    float tz0 = htanh(0.5f * z0);
                    float tz1 = htanh(0.5f * z1);
                    float th0 = htanh(h0);
                    float th1 = htanh(h1);
                    hacc = fmaf(sp2[2 * q],     (1.f - tz0) * th0, hacc);
                    hacc = fmaf(sp2[2 * q + 1], (1.f - tz1) * th1, hacc);
                }
                float hr = fmaxf(hacc, 0.f);     // relu

                float myout = 0.f;
                #pragma unroll
                for (int p = 0; p < PP; ++p) {
                    float v = hr * sow[p * OO + lane];
                    v += __shfl_xor_sync(FULL, v, 16);
                    v += __shfl_xor_sync(FULL, v, 8);
                    v += __shfl_xor_sync(FULL, v, 4);
                    v += __shfl_xor_sync(FULL, v, 2);
                    v += __shfl_xor_sync(FULL, v, 1);
                    if (lane == p) myout = v + sob[p];
                }
                if (lane < PP) out[(base + i) * PP + lane] = myout;
            }
            __syncwarp();                    // buf reads done before next pair
        }
    }
}

// ---------------------------------------------------------------------------
extern "C" void kernel_launch(void* const* d_in, const int* in_sizes, int n_in,
                              void* d_out, int out_size) {
    const float* x    = (const float*)d_in[0];
    const int*   ei   = (const int*)  d_in[1];
    const float* Wz   = (const float*)d_in[2];
    const float* bz   = (const float*)d_in[3];
    // d_in[4], d_in[5]: Wr, br — dead code (H == 0 kills the reset gate)
    const float* Wh   = (const float*)d_in[6];
    const float* bh   = (const float*)d_in[7];
    const float* lzw  = (const float*)d_in[8];
    const float* lzb  = (const float*)d_in[9];
    // d_in[10], d_in[11]: lr_w, lr_b — unused
    const float* lhw  = (const float*)d_in[12];
    const float* lhb  = (const float*)d_in[13];
    const float* att  = (const float*)d_in[14];
    const float* outw = (const float*)d_in[15];
    const float* outb = (const float*)d_in[16];
    float* out = (float*)d_out;

    fused_kernel<<<NBLK, NTHR>>>(x, ei, Wz, bz, Wh, bh, lzw, lzb, lhw, lhb,
                                 att, outw, outb, out);
}